// round 14
// baseline (speedup 1.0000x reference)
#include <cuda_runtime.h>
#include <cuda_fp16.h>
#include <math.h>
#include <stdint.h>

// ---------------- problem constants ----------------
#define Bz   16
#define T0   400
#define F0c  40
#define Hc   512
#define T1c  396
#define T3c  384
#define Kbot (Hc*Hc)   // 262144

// weight arena offsets (elements)
#define WO1 0
#define WO2 102400
#define WO3 888832
#define WO4 1675264
#define WO5 1937408
#define WTOT 2199552

// ---------------- scratch ----------------
__device__ float g_bufA[Bz*Hc*T1c];
__device__ float g_bufB[Bz*Hc*T1c];
__device__ uint32_t g_act[Bz*F0c*T0];        // packed split input
__device__ __half g_wH[WTOT];
__device__ __half g_wL[WTOT];
__device__ __half g_x5H[Bz*Hc*T3c];
__device__ __half g_x5L[Bz*Hc*T3c];
__device__ uint32_t g_M[Bz*Kbot];            // pooled matrices, packed (lo16|hi16)
__device__ float g_sums[5][Hc];
__device__ float g_sumsqs[5][Hc];
__device__ float g_h[Bz*Hc];
__device__ float g_zero[Hc];

// ---------------- helpers ----------------
__device__ __forceinline__ float relu20(float v)
{
    return fminf(fmaxf(v, 0.f), 20.f);
}

__device__ __forceinline__ uint32_t f16_split_pack(float v)
{
    __half h = __float2half_rn(v);
    __half l = __float2half_rn(v - __half2float(h));
    return ((uint32_t)__half_as_ushort(l) << 16) | (uint32_t)__half_as_ushort(h);
}

__device__ __forceinline__ void f16_split2(float x0, float x1, uint32_t& hw, uint32_t& lw)
{
    __half2 h = __floats2half2_rn(x0, x1);
    float2 hf = __half22float2(h);
    __half2 l = __floats2half2_rn(x0 - hf.x, x1 - hf.y);
    hw = *(uint32_t*)&h;
    lw = *(uint32_t*)&l;
}

__device__ __forceinline__ void mma_f16_k16(float* d, const uint32_t* a, const uint32_t* b)
{
    asm volatile(
        "mma.sync.aligned.m16n8k16.row.col.f32.f16.f16.f32 "
        "{%0,%1,%2,%3}, {%4,%5,%6,%7}, {%8,%9}, {%0,%1,%2,%3};"
        : "+f"(d[0]), "+f"(d[1]), "+f"(d[2]), "+f"(d[3])
        : "r"(a[0]), "r"(a[1]), "r"(a[2]), "r"(a[3]), "r"(b[0]), "r"(b[1]));
}

__device__ __forceinline__ void ldsm_x4(uint32_t* r, uint32_t saddr)
{
    asm volatile("ldmatrix.sync.aligned.m8n8.x4.shared.b16 {%0,%1,%2,%3}, [%4];"
        : "=r"(r[0]), "=r"(r[1]), "=r"(r[2]), "=r"(r[3]) : "r"(saddr));
}

__device__ __forceinline__ void sts_v2(uint32_t saddr, uint32_t v0, uint32_t v1)
{
    asm volatile("st.shared.v2.u32 [%0], {%1,%2};" :: "r"(saddr), "r"(v0), "r"(v1));
}

__device__ __forceinline__ void cp_async16(uint32_t saddr, const void* gaddr)
{
    asm volatile("cp.async.cg.shared.global [%0], [%1], 16;"
        :: "r"(saddr), "l"(gaddr));
}
#define CP_COMMIT() asm volatile("cp.async.commit_group;")
#define CP_WAIT1()  asm volatile("cp.async.wait_group 1;")

// ---------------- prep ----------------
__global__ void prep(const float* __restrict__ in,
                     const float* __restrict__ w1, const float* __restrict__ w2,
                     const float* __restrict__ w3, const float* __restrict__ w4,
                     const float* __restrict__ w5)
{
    int i = blockIdx.x * blockDim.x + threadIdx.x;
    if (i < WTOT) {
        float v;
        if (i < WO2)      v = w1[i];
        else if (i < WO3) v = w2[i - WO2];
        else if (i < WO4) v = w3[i - WO3];
        else if (i < WO5) v = w4[i - WO4];
        else              v = w5[i - WO5];
        __half h = __float2half_rn(v);
        g_wH[i] = h;
        g_wL[i] = __float2half_rn(v - __half2float(h));
    }
    if (i < Bz * T0 * F0c) {
        int c = i % F0c;
        int t = (i / F0c) % T0;
        int b = i / (F0c * T0);
        g_act[(b * F0c + c) * T0 + t] = f16_split_pack(in[i]);
    }
    if (i < 5 * Hc) {
        (&g_sums[0][0])[i] = 0.f;
        (&g_sumsqs[0][0])[i] = 0.f;
    }
    if (i < Bz * Hc) {
        g_h[i] = 0.f;
    }
}

// ---------------- BN finalize+apply+clamp+split to separate hi/lo planes (x5 only) ----
__global__ __launch_bounds__(512)
void split_bn_sep(const float* __restrict__ Y, __half* __restrict__ dH,
                  __half* __restrict__ dL,
                  const float* __restrict__ sums, const float* __restrict__ sumsqs,
                  const float* __restrict__ gamma, const float* __restrict__ beta,
                  float invN, int T, int total)
{
    __shared__ float sSc[Hc];
    __shared__ float sSh[Hc];
    {
        int c = threadIdx.x;
        float s = sums[c], q = sumsqs[c];
        float m = s * invN;
        float var = q * invN - m * m;
        float a = gamma[c] * rsqrtf(var + 1e-5f);
        sSc[c] = a;
        sSh[c] = beta[c] - a * m;
    }
    __syncthreads();
    for (int idx = blockIdx.x * 512 + threadIdx.x; idx < total; idx += gridDim.x * 512) {
        int c = (idx / T) & (Hc - 1);
        float v = relu20(sSc[c] * Y[idx] + sSh[c]);
        __half h = __float2half_rn(v);
        dH[idx] = h;
        dL[idx] = __float2half_rn(v - __half2float(h));
    }
}

// ---------------- FP16x3 conv-as-GEMM with fused input BN ----------------
// A: pre-split fp16 hi/lo planes, cp.async 3-stage.
// B: MODE 0 = packed pre-split uint32 (conv1 input);
//    MODE 1 = raw fp32, BN by k-channel (smem table from sums arrays) + clamp + split;
//    MODE 2 = raw fp32, BN by n-channel (per-thread register scale) + clamp + split.
// B gathered at prefetch distance 2. STATS: per-row sum/sumsq of (acc+bias).
// PACK: write packed (lo|hi) uint32 output (pooling -> M).
#define RSTR 12
#define ASTG_B (128 * RSTR * 4)
#define BSTG_B (64 * RSTR * 4)
template<int KW, int DIL, int MODE, bool STATS, bool PACK>
__global__ __launch_bounds__(256, 3)
void conv_gemm(const __half* __restrict__ AH, const __half* __restrict__ AL,
               const float* __restrict__ bias,
               const void* __restrict__ X_, float* __restrict__ Y,
               float* __restrict__ oSum, float* __restrict__ oSumsq,
               const float* __restrict__ iSum, const float* __restrict__ iSumsq,
               const float* __restrict__ gB, const float* __restrict__ bB, float invN,
               int C, int Tin, int Tout, int CK, int Ntot,
               int strideA, int strideX, int strideY)
{
    AH += (size_t)blockIdx.z * strideA;
    AL += (size_t)blockIdx.z * strideA;
    Y  += (size_t)blockIdx.z * strideY;

    __shared__ uint32_t AsH[3][128][RSTR];
    __shared__ uint32_t AsL[3][128][RSTR];
    __shared__ uint32_t BsH[2][64][RSTR];
    __shared__ uint32_t BsL[2][64][RSTR];
    __shared__ float sScB[Hc];
    __shared__ float sShB[Hc];

    const int tid  = threadIdx.x;
    const int lane = tid & 31;
    const int warp = tid >> 5;
    const int wm = warp >> 1;
    const int wn = warp & 1;
    const int oBase = blockIdx.y * 128;
    const int nBase = blockIdx.x * 64;

    float acc[2][4][4];
    #pragma unroll
    for (int i = 0; i < 2; i++)
        #pragma unroll
        for (int j = 0; j < 4; j++)
            #pragma unroll
            for (int r = 0; r < 4; r++) acc[i][j][r] = 0.f;

    const int aRow = tid >> 1;
    const int bN  = tid & 63;
    const int bG  = tid >> 6;

    const int nIdx = nBase + bN;
    const bool nValid = (nIdx < Ntot);
    int nb = 0, nt0 = 0;
    if (nValid) { nb = nIdx / Tout; nt0 = nIdx - nb * Tout; }

    const uint32_t* Xu = (const uint32_t*)X_ + (size_t)blockIdx.z * strideX
                         + ((size_t)nb * C) * Tin + nt0;
    const float*    Xf = (const float*)X_ + (size_t)blockIdx.z * strideX
                         + ((size_t)nb * C) * Tin + nt0;

    const __half* ArowH = AH + (size_t)(oBase + aRow) * CK + (tid & 1) * 8;
    const __half* ArowL = AL + (size_t)(oBase + aRow) * CK + (tid & 1) * 8;

    const uint32_t baseAH = (uint32_t)__cvta_generic_to_shared(&AsH[0][0][0]);
    const uint32_t baseAL = (uint32_t)__cvta_generic_to_shared(&AsL[0][0][0]);
    const uint32_t baseBH = (uint32_t)__cvta_generic_to_shared(&BsH[0][0][0]);
    const uint32_t baseBL = (uint32_t)__cvta_generic_to_shared(&BsL[0][0][0]);

    const uint32_t stA = (aRow * RSTR + (tid & 1) * 4) * 4;
    const uint32_t stB = (bN * RSTR + bG * 2) * 4;

    const int aFragRow = (lane & 7) + ((lane >> 3) & 1) * 8;
    const int aFragWord = (lane >> 4) * 4;
    const uint32_t ldA0 = ((wm * 32 + aFragRow) * RSTR + aFragWord) * 4;
    const int bFragRow = (lane & 7) + ((lane >> 4) << 3);
    const int bFragWord = ((lane >> 3) & 1) * 4;
    const uint32_t ldB0 = ((wn * 32 + bFragRow) * RSTR + bFragWord) * 4;

    // ---- input BN constants ----
    float bSc = 1.f, bSh = 0.f;   // MODE 2 per-thread (channel = n)
    if (MODE == 1) {
        for (int c = tid; c < C; c += 256) {
            float s = iSum[c], q = iSumsq[c];
            float m = s * invN;
            float var = q * invN - m * m;
            float a = gB[c] * rsqrtf(var + 1e-5f);
            sScB[c] = a;
            sShB[c] = bB[c] - a * m;
        }
        __syncthreads();
    }
    if (MODE == 2 && nValid) {
        int ch = nIdx & (Hc - 1);
        float s = iSum[ch], q = iSumsq[ch];
        float m = s * invN;
        float var = q * invN - m * m;
        bSc = gB[ch] * rsqrtf(var + 1e-5f);
        bSh = bB[ch] - bSc * m;
    }

    const int nSteps = (CK + 15) >> 4;

    // B gather at distance 2; for MODE 1/2 the stored bits are BN'd floats
    uint32_t pbw[2][4];
    #pragma unroll
    for (int set = 0; set < 2; set++) {
        int k0 = set * 16;
        #pragma unroll
        for (int p = 0; p < 4; p++) {
            int kkg = k0 + bG * 4 + p;
            uint32_t v = 0;
            if (nValid && kkg < CK && set < nSteps) {
                int c = kkg / KW;
                int kw = kkg - c * KW;
                if (MODE == 0) {
                    v = Xu[c * Tin + kw * DIL];
                } else {
                    float f = Xf[c * Tin + kw * DIL];
                    if (MODE == 1) f = relu20(sScB[c] * f + sShB[c]);
                    else           f = relu20(bSc * f + bSh);
                    v = __float_as_uint(f);
                }
            }
            pbw[set][p] = v;
        }
    }

    cp_async16(baseAH + stA, ArowH);
    cp_async16(baseAL + stA, ArowL);
    CP_COMMIT();
    if (1 < nSteps) {
        cp_async16(baseAH + ASTG_B + stA, ArowH + 16);
        cp_async16(baseAL + ASTG_B + stA, ArowL + 16);
    }
    CP_COMMIT();

    // stage B[0]
    {
        uint32_t h0, h1, l0, l1;
        if (MODE == 0) {
            h0 = __byte_perm(pbw[0][0], pbw[0][1], 0x5410);
            h1 = __byte_perm(pbw[0][2], pbw[0][3], 0x5410);
            l0 = __byte_perm(pbw[0][0], pbw[0][1], 0x7632);
            l1 = __byte_perm(pbw[0][2], pbw[0][3], 0x7632);
        } else {
            f16_split2(__uint_as_float(pbw[0][0]), __uint_as_float(pbw[0][1]), h0, l0);
            f16_split2(__uint_as_float(pbw[0][2]), __uint_as_float(pbw[0][3]), h1, l1);
        }
        sts_v2(baseBH + stB, h0, h1);
        sts_v2(baseBL + stB, l0, l1);
    }
    CP_WAIT1();
    __syncthreads();

    for (int s = 0; s < nSteps; s++) {
        // LDG B[s+2]
        if (s + 2 < nSteps) {
            int k0 = (s + 2) * 16;
            #pragma unroll
            for (int p = 0; p < 4; p++) {
                int kkg = k0 + bG * 4 + p;
                uint32_t v = 0;
                if (nValid && kkg < CK) {
                    int c = kkg / KW;
                    int kw = kkg - c * KW;
                    if (MODE == 0) {
                        v = Xu[c * Tin + kw * DIL];
                    } else {
                        float f = Xf[c * Tin + kw * DIL];
                        if (MODE == 1) f = relu20(sScB[c] * f + sShB[c]);
                        else           f = relu20(bSc * f + bSh);
                        v = __float_as_uint(f);
                    }
                }
                pbw[s & 1][p] = v;
            }
        }

        // STS B[s+1]
        if (s + 1 < nSteps) {
            const uint32_t* pw = pbw[(s + 1) & 1];
            const uint32_t offB = ((s + 1) & 1) * BSTG_B;
            uint32_t h0, h1, l0, l1;
            if (MODE == 0) {
                h0 = __byte_perm(pw[0], pw[1], 0x5410);
                h1 = __byte_perm(pw[2], pw[3], 0x5410);
                l0 = __byte_perm(pw[0], pw[1], 0x7632);
                l1 = __byte_perm(pw[2], pw[3], 0x7632);
            } else {
                f16_split2(__uint_as_float(pw[0]), __uint_as_float(pw[1]), h0, l0);
                f16_split2(__uint_as_float(pw[2]), __uint_as_float(pw[3]), h1, l1);
            }
            sts_v2(baseBH + offB + stB, h0, h1);
            sts_v2(baseBL + offB + stB, l0, l1);
        }

        // cp.async A[s+2]
        if (s + 2 < nSteps) {
            int k0 = (s + 2) * 16;
            const uint32_t offA = ((s + 2) % 3) * ASTG_B;
            cp_async16(baseAH + offA + stA, ArowH + k0);
            cp_async16(baseAL + offA + stA, ArowL + k0);
        }
        CP_COMMIT();

        // consume step s
        {
            const uint32_t offA = (s % 3) * ASTG_B;
            const uint32_t offB = (s & 1) * BSTG_B;
            uint32_t bHf[8], bLf[8];
            ldsm_x4(bHf,     baseBH + offB + ldB0);
            ldsm_x4(bHf + 4, baseBH + offB + ldB0 + 16 * RSTR * 4);
            ldsm_x4(bLf,     baseBL + offB + ldB0);
            ldsm_x4(bLf + 4, baseBL + offB + ldB0 + 16 * RSTR * 4);
            #pragma unroll
            for (int mt = 0; mt < 2; mt++) {
                const uint32_t mtOff = mt * 16 * RSTR * 4;
                uint32_t aHf[4], aLf[4];
                ldsm_x4(aHf, baseAH + offA + ldA0 + mtOff);
                ldsm_x4(aLf, baseAL + offA + ldA0 + mtOff);
                #pragma unroll
                for (int nt = 0; nt < 4; nt++) {
                    mma_f16_k16(acc[mt][nt], aHf, bLf + nt * 2);
                    mma_f16_k16(acc[mt][nt], aLf, bHf + nt * 2);
                    mma_f16_k16(acc[mt][nt], aHf, bHf + nt * 2);
                }
            }
        }

        CP_WAIT1();
        __syncthreads();
    }

    // epilogue
    #pragma unroll
    for (int mt = 0; mt < 2; mt++) {
        int row0 = oBase + wm * 32 + mt * 16 + (lane >> 2);
        float b0 = bias[row0];
        float b1 = bias[row0 + 8];
        float s0 = 0.f, q0 = 0.f, s1 = 0.f, q1 = 0.f;
        #pragma unroll
        for (int nt = 0; nt < 4; nt++) {
            int col0 = nBase + wn * 32 + nt * 8 + (lane & 3) * 2;
            #pragma unroll
            for (int cc = 0; cc < 2; cc++) {
                int col = col0 + cc;
                if (col < Ntot) {
                    float v0 = acc[mt][nt][cc]     + b0;
                    float v1 = acc[mt][nt][2 + cc] + b1;
                    int b = col / Tout;
                    int t = col - b * Tout;
                    size_t base = ((size_t)b * Hc) * Tout + t;
                    if (PACK) {
                        Y[base + (size_t)row0 * Tout]       = __uint_as_float(f16_split_pack(v0));
                        Y[base + (size_t)(row0 + 8) * Tout] = __uint_as_float(f16_split_pack(v1));
                    } else {
                        Y[base + (size_t)row0 * Tout]       = v0;
                        Y[base + (size_t)(row0 + 8) * Tout] = v1;
                    }
                    if (STATS) {
                        s0 += v0; q0 += v0 * v0;
                        s1 += v1; q1 += v1 * v1;
                    }
                }
            }
        }
        if (STATS) {
            #pragma unroll
            for (int off = 2; off >= 1; off >>= 1) {
                s0 += __shfl_down_sync(0xffffffffu, s0, off);
                q0 += __shfl_down_sync(0xffffffffu, q0, off);
                s1 += __shfl_down_sync(0xffffffffu, s1, off);
                q1 += __shfl_down_sync(0xffffffffu, q1, off);
            }
            if ((lane & 3) == 0) {
                atomicAdd(&oSum[row0], s0);
                atomicAdd(&oSumsq[row0], q0);
                atomicAdd(&oSum[row0 + 8], s1);
                atomicAdd(&oSumsq[row0 + 8], q1);
            }
        }
    }
}

// ---------------- bottleneck (tensor-core, fp16x3) ----------------
__global__ __launch_bounds__(256)
void bottleneck_tc(const float* __restrict__ W)
{
    const int lane = threadIdx.x & 31;
    const int warp = threadIdx.x >> 5;
    const int o0 = blockIdx.x * 64 + warp * 8;
    const int kb = blockIdx.y * 4096;

    const int r  = lane >> 2;
    const int kq = (lane & 3) * 2;

    const uint32_t* m0 = g_M + (size_t)r * Kbot + kb + kq;
    const uint32_t* m1 = g_M + (size_t)(r + 8) * Kbot + kb + kq;
    const float*    w0 = W + (size_t)(o0 + r) * Kbot + kb + kq;

    float acc[4] = {0.f, 0.f, 0.f, 0.f};

    #pragma unroll 2
    for (int s = 0; s < 4096; s += 16) {
        uint2 u0 = *(const uint2*)(m0 + s);
        uint2 u2 = *(const uint2*)(m0 + s + 8);
        uint2 u1 = *(const uint2*)(m1 + s);
        uint2 u3 = *(const uint2*)(m1 + s + 8);
        float2 wv0 = *(const float2*)(w0 + s);
        float2 wv1 = *(const float2*)(w0 + s + 8);

        uint32_t aH[4], aL[4];
        aH[0] = __byte_perm(u0.x, u0.y, 0x5410);  aL[0] = __byte_perm(u0.x, u0.y, 0x7632);
        aH[1] = __byte_perm(u1.x, u1.y, 0x5410);  aL[1] = __byte_perm(u1.x, u1.y, 0x7632);
        aH[2] = __byte_perm(u2.x, u2.y, 0x5410);  aL[2] = __byte_perm(u2.x, u2.y, 0x7632);
        aH[3] = __byte_perm(u3.x, u3.y, 0x5410);  aL[3] = __byte_perm(u3.x, u3.y, 0x7632);

        uint32_t bH[2], bL[2];
        f16_split2(wv0.x, wv0.y, bH[0], bL[0]);
        f16_split2(wv1.x, wv1.y, bH[1], bL[1]);

        mma_f16_k16(acc, aH, bL);
        mma_f16_k16(acc, aL, bH);
        mma_f16_k16(acc, aH, bH);
    }

    int o = o0 + kq;
    atomicAdd(&g_h[r * Hc + o],           acc[0]);
    atomicAdd(&g_h[r * Hc + o + 1],       acc[1]);
    atomicAdd(&g_h[(r + 8) * Hc + o],     acc[2]);
    atomicAdd(&g_h[(r + 8) * Hc + o + 1], acc[3]);
}

// ---------------- fused bn2d + embedding + L2-norm ----------------
__global__ __launch_bounds__(512)
void emb_fused(const float* __restrict__ bot_b,
               const float* __restrict__ gg, const float* __restrict__ gb,
               const float* __restrict__ Wemb, const float* __restrict__ bemb,
               float* __restrict__ out)
{
    __shared__ float hs[Hc];
    __shared__ float es[Hc];
    __shared__ float red[Hc];

    const int b = blockIdx.x;
    const int o = threadIdx.x;
    const int warp = o >> 5, lane = o & 31;

    {
        float bb = bot_b[o];
        float s = 0.f, q = 0.f, vb = 0.f;
        #pragma unroll
        for (int i = 0; i < Bz; i++) {
            float x = g_h[i * Hc + o] + bb;
            s += x; q += x * x;
            if (i == b) vb = x;
        }
        float m = s * (1.f / 16.f);
        float var = q * (1.f / 16.f) - m * m;
        float a = gg[o] * rsqrtf(var + 1e-5f);
        float d = gb[o] - a * m;
        hs[o] = relu20(a * vb + d);
    }
    __syncthreads();

    for (int e = warp; e < Hc; e += 16) {
        float s = 0.f;
        for (int c = lane; c < Hc; c += 32)
            s += hs[c] * Wemb[e * Hc + c];
        #pragma unroll
        for (int off = 16; off; off >>= 1)
            s += __shfl_down_sync(0xffffffffu, s, off);
        if (lane == 0) es[e] = s + bemb[e];
    }
    __syncthreads();

    float v = es[o];
    red[o] = v * v;
    __syncthreads();
    for (int st = 256; st > 0; st >>= 1) {
        if (o < st) red[o] += red[o + st];
        __syncthreads();
    }
    float scale = 10.f / sqrtf(red[0] + 1e-10f);
    out[b * Hc + o] = v * scale;
}

// ---------------- launcher ----------------
extern "C" void kernel_launch(void* const* d_in, const int* in_sizes, int n_in,
                              void* d_out, int out_size)
{
    const float* input_x = (const float*)d_in[0];
    const float* conv1_b = (const float*)d_in[2];
    const float* bn1_g   = (const float*)d_in[3];
    const float* bn1_b   = (const float*)d_in[4];
    const float* conv2_b = (const float*)d_in[6];
    const float* bn2_g   = (const float*)d_in[7];
    const float* bn2_b   = (const float*)d_in[8];
    const float* conv3_b = (const float*)d_in[10];
    const float* bn3_g   = (const float*)d_in[11];
    const float* bn3_b   = (const float*)d_in[12];
    const float* lin4_b  = (const float*)d_in[14];
    const float* bn4_g   = (const float*)d_in[15];
    const float* bn4_b   = (const float*)d_in[16];
    const float* lin5_b  = (const float*)d_in[18];
    const float* bn5_g   = (const float*)d_in[19];
    const float* bn5_b   = (const float*)d_in[20];
    const float* bot_w   = (const float*)d_in[21];
    const float* bot_b   = (const float*)d_in[22];
    const float* bnb_g   = (const float*)d_in[23];
    const float* bnb_b   = (const float*)d_in[24];
    const float* emb_w   = (const float*)d_in[25];
    const float* emb_b   = (const float*)d_in[26];
    float* out = (float*)d_out;

    float *pA, *pB, *pZero, *pMf, *pSums, *pSumsqs;
    uint32_t *pAct;
    __half *pWH, *pWL, *pX5H, *pX5L;
    cudaGetSymbolAddress((void**)&pA,     g_bufA);
    cudaGetSymbolAddress((void**)&pB,     g_bufB);
    cudaGetSymbolAddress((void**)&pAct,   g_act);
    cudaGetSymbolAddress((void**)&pWH,    g_wH);
    cudaGetSymbolAddress((void**)&pWL,    g_wL);
    cudaGetSymbolAddress((void**)&pX5H,   g_x5H);
    cudaGetSymbolAddress((void**)&pX5L,   g_x5L);
    cudaGetSymbolAddress((void**)&pMf,    g_M);
    cudaGetSymbolAddress((void**)&pZero,  g_zero);
    cudaGetSymbolAddress((void**)&pSums,  g_sums);
    cudaGetSymbolAddress((void**)&pSumsqs,g_sumsqs);

    prep<<<(WTOT + 255) / 256, 256>>>(input_x,
        (const float*)d_in[1], (const float*)d_in[5], (const float*)d_in[9],
        (const float*)d_in[13], (const float*)d_in[17]);

    // conv1: MODE0 (packed input). CK=200, T 400->396, N=6336 -> bufA
    conv_gemm<5,1,0,true,false><<<dim3(99, 4, 1), 256>>>(
        pWH + WO1, pWL + WO1, conv1_b, pAct, pA,
        pSums + 0*Hc, pSumsqs + 0*Hc,
        nullptr, nullptr, nullptr, nullptr, 0.f,
        40, 400, 396, 200, 6336, 0, 0, 0);

    // conv2: MODE1 (raw bufA + bn1). CK=1536, T 396->392, N=6272 -> bufB
    conv_gemm<3,2,1,true,false><<<dim3(98, 4, 1), 256>>>(
        pWH + WO2, pWL + WO2, conv2_b, pA, pB,
        pSums + 1*Hc, pSumsqs + 1*Hc,
        pSums + 0*Hc, pSumsqs + 0*Hc, bn1_g, bn1_b, 1.f / 6336.f,
        512, 396, 392, 1536, 6272, 0, 0, 0);

    // conv3: MODE1 (raw bufB + bn2). CK=1536, T 392->384, N=6144 -> bufA
    conv_gemm<3,4,1,true,false><<<dim3(96, 4, 1), 256>>>(
        pWH + WO3, pWL + WO3, conv3_b, pB, pA,
        pSums + 2*Hc, pSumsqs + 2*Hc,
        pSums + 1*Hc, pSumsqs + 1*Hc, bn2_g, bn2_b, 1.f / 6272.f,
        512, 392, 384, 1536, 6144, 0, 0, 0);

    // lin4: MODE1 (raw bufA + bn3). CK=512, T=384 -> bufB (x4 raw)
    conv_gemm<1,1,1,true,false><<<dim3(96, 4, 1), 256>>>(
        pWH + WO4, pWL + WO4, lin4_b, pA, pB,
        pSums + 3*Hc, pSumsqs + 3*Hc,
        pSums + 2*Hc, pSumsqs + 2*Hc, bn3_g, bn3_b, 1.f / 6144.f,
        512, 384, 384, 512, 6144, 0, 0, 0);

    // lin5: MODE1 (raw bufB(x4) + bn4). CK=512 -> bufA (x5 raw)
    conv_gemm<1,1,1,true,false><<<dim3(96, 4, 1), 256>>>(
        pWH + WO5, pWL + WO5, lin5_b, pB, pA,
        pSums + 4*Hc, pSumsqs + 4*Hc,
        pSums + 3*Hc, pSumsqs + 3*Hc, bn4_g, bn4_b, 1.f / 6144.f,
        512, 384, 384, 512, 6144, 0, 0, 0);

    // x5 planes: bn5 applied to raw x5
    split_bn_sep<<<148, 512>>>(pA, pX5H, pX5L,
                               pSums + 4*Hc, pSumsqs + 4*Hc, bn5_g, bn5_b,
                               1.f / 6144.f, 384, Bz * Hc * 384);

    // pooling: MODE2 (A = x5 planes, B = raw x4 + bn4 by n), PACK -> g_M
    conv_gemm<1,1,2,false,true><<<dim3(8, 4, 16), 256>>>(
        pX5H, pX5L, pZero, pB, pMf,
        nullptr, nullptr,
        pSums + 3*Hc, pSumsqs + 3*Hc, bn4_g, bn4_b, 1.f / 6144.f,
        384, 1, 1, 384, 512, Hc * T3c, Hc * T3c, Kbot);

    // bottleneck: tensor-core fp16x3 (g_h zeroed by prep)
    bottleneck_tc<<<dim3(8, 64), 256>>>(bot_w);

    // fused bn2d + embedding + norm
    emb_fused<<<16, 512>>>(bot_b, bnb_g, bnb_b, emb_w, emb_b, out);
}